// round 3
// baseline (speedup 1.0000x reference)
#include <cuda_runtime.h>
#include <cstdint>

#define THREADS 512
typedef unsigned long long ull;

// smem layout in ull (float2) units
#define OFF_X  0        // xbuf: [ic16][19 rows][20 cols]  = 6080 ull (dup-packed x)
#define OFF_W  6080     // wbuf: [ic16][op8][10 taps]      = 1280 ull (oc-pair packed w)
#define OFF_Z  7360     // z2buf:[op8][36 rows][37 cols]   = 10656 ull (oc-pair packed z2)
#define OFF_T  18016    // tbuf: [op8][32 rows][36 cols]   = 9216 ull
#define SMEM_BYTES ((18016 + 9216) * 8)   // 217856

__device__ __forceinline__ ull pack2(float v) {
    ull r; asm("mov.b64 %0, {%1, %1};" : "=l"(r) : "f"(v)); return r;
}
__device__ __forceinline__ ull packf2(float a, float b) {
    ull r; asm("mov.b64 %0, {%1, %2};" : "=l"(r) : "f"(a), "f"(b)); return r;
}
__device__ __forceinline__ void fma2(ull &acc, ull x, ull w) {
    asm("fma.rn.f32x2 %0, %1, %2, %0;" : "+l"(acc) : "l"(x), "l"(w));
}

// One fused kernel: z2 = W (*) x-upsampled (parity-sparse transposed conv),
// then y = G (*) z2 (separable 4-tap FIR), all through shared memory.
__global__ __launch_bounds__(THREADS, 1)
void conv_resample_kernel(const float* __restrict__ x, const float* __restrict__ f,
                          const float* __restrict__ w, float* __restrict__ out) {
    extern __shared__ ull sm[];
    ull* xb = sm + OFF_X;
    ull* wb = sm + OFF_W;
    ull* zb = sm + OFF_Z;
    ull* tb = sm + OFF_T;

    const int tid = threadIdx.x;
    const int tile = blockIdx.x;           // 256 tiles of 16x16 low-res
    const int g = blockIdx.y;
    const int n = blockIdx.z;
    const int ty = tile >> 4, tx = tile & 15;
    const int a0 = ty * 16, b0 = tx * 16;  // low-res tile origin

    // ---- stage 1: x tile (19x19 low-res + zero halo), duplicated-packed ----
    const float* xg = x + ((size_t)(n * 128 + g * 16)) * 65536;
    for (int i = tid; i < 16 * 19 * 19; i += THREADS) {
        int c = i % 19;
        int r = (i / 19) % 19;
        int ic = i / 361;
        int gm = a0 - 2 + r, gq = b0 - 2 + c;
        float v = (gm >= 0 && gm < 256 && gq >= 0 && gq < 256)
                    ? xg[ic * 65536 + gm * 256 + gq] : 0.f;
        xb[(ic * 19 + r) * 20 + c] = pack2(v);
    }

    // ---- stage 1b: weights as oc-pair float2, layout [ic][ocpair][tap] ----
    const float* wgp = w + ((size_t)g * 16) * 144;   // 16 oc x 16 ic x 9
    for (int i = tid; i < 16 * 8 * 9; i += THREADS) {
        int tap = i % 9;
        int op = (i / 9) % 8;
        int ic = i / 72;
        float w0 = wgp[((op * 2 + 0) * 16 + ic) * 9 + tap];
        float w1 = wgp[((op * 2 + 1) * 16 + ic) * 9 + tap];
        wb[(ic * 8 + op) * 10 + tap] = packf2(w0, w1);
    }
    __syncthreads();

    // ---- stage 2: z2 phases. unit = (low-res row ar(18), col-strip(6 of 3), ocpair(8)) ----
    for (int u = tid; u < 864; u += THREADS) {
        int op = u & 7;
        int v = u >> 3;
        int strip = v % 6;
        int ar = v / 6;                    // 0..17
        int cp = strip * 3;                // position cols cp..cp+2, x cols cp..cp+3

        ull acc[3][4];
#pragma unroll
        for (int p = 0; p < 3; ++p)
#pragma unroll
            for (int q = 0; q < 4; ++q) acc[p][q] = 0ull;

#pragma unroll 4
        for (int ic = 0; ic < 16; ++ic) {
            const ull* xr = xb + (ic * 19 + ar) * 20 + cp;
            ull x00 = xr[0],  x01 = xr[1],  x02 = xr[2],  x03 = xr[3];
            ull x10 = xr[20], x11 = xr[21], x12 = xr[22], x13 = xr[23];
            const ull* wp = wb + (ic * 8 + op) * 10;
            ull w0 = wp[0], w1 = wp[1], w2 = wp[2], w3 = wp[3], w4 = wp[4],
                w5 = wp[5], w6 = wp[6], w7 = wp[7], w8 = wp[8];
            // pos 0 (x cols 0,1)
            fma2(acc[0][0], x00, w0); fma2(acc[0][0], x01, w2);
            fma2(acc[0][0], x10, w6); fma2(acc[0][0], x11, w8);
            fma2(acc[0][1], x01, w1); fma2(acc[0][1], x11, w7);
            fma2(acc[0][2], x10, w3); fma2(acc[0][2], x11, w5);
            fma2(acc[0][3], x11, w4);
            // pos 1 (x cols 1,2)
            fma2(acc[1][0], x01, w0); fma2(acc[1][0], x02, w2);
            fma2(acc[1][0], x11, w6); fma2(acc[1][0], x12, w8);
            fma2(acc[1][1], x02, w1); fma2(acc[1][1], x12, w7);
            fma2(acc[1][2], x11, w3); fma2(acc[1][2], x12, w5);
            fma2(acc[1][3], x12, w4);
            // pos 2 (x cols 2,3)
            fma2(acc[2][0], x02, w0); fma2(acc[2][0], x03, w2);
            fma2(acc[2][0], x12, w6); fma2(acc[2][0], x13, w8);
            fma2(acc[2][1], x03, w1); fma2(acc[2][1], x13, w7);
            fma2(acc[2][2], x12, w3); fma2(acc[2][2], x13, w5);
            fma2(acc[2][3], x13, w4);
        }
        // store 4 phases: rows r2 = 2*ar + py, cols c2 = 2*(cp+p) + px
        ull* zr0 = zb + ((size_t)op * 36 + 2 * ar) * 37 + 2 * cp;
        ull* zr1 = zr0 + 37;
#pragma unroll
        for (int p = 0; p < 3; ++p) {
            zr0[2 * p]     = acc[p][0];
            zr0[2 * p + 1] = acc[p][1];
            zr1[2 * p]     = acc[p][2];
            zr1[2 * p + 1] = acc[p][3];
        }
    }

    // FIR coefficients g[a] = 2*f[3-a], packed for oc-pair lanes
    float f0 = __ldg(f), f1 = __ldg(f + 1), f2 = __ldg(f + 2), f3 = __ldg(f + 3);
    ull gp0 = pack2(2.f * f3), gp1 = pack2(2.f * f2),
        gp2 = pack2(2.f * f1), gp3 = pack2(2.f * f0);
    __syncthreads();

    // ---- stage 3a: vertical FIR  t[op][oyl][tc] = sum_ay g[ay]*z2[r2=oyl+ay+1][c2=tc+1] ----
    for (int i = tid; i < 8 * 32 * 35; i += THREADS) {
        int tc = i % 35;
        int oyl = (i / 35) % 32;
        int op = i / 1120;
        const ull* zc = zb + ((size_t)op * 36 + oyl + 1) * 37 + (tc + 1);
        ull a = 0ull;
        fma2(a, zc[0],   gp0);
        fma2(a, zc[37],  gp1);
        fma2(a, zc[74],  gp2);
        fma2(a, zc[111], gp3);
        tb[((size_t)op * 32 + oyl) * 36 + tc] = a;
    }
    __syncthreads();

    // ---- stage 3b: horizontal FIR + store ----
    float* og = out + ((size_t)(n * 128 + g * 16)) * 262144;
    const int oy0 = a0 * 2, ox0 = b0 * 2;
    for (int i = tid; i < 8192; i += THREADS) {
        int oxl = i & 31;
        int oyl = (i >> 5) & 31;
        int op = i >> 10;
        const ull* tc = tb + ((size_t)op * 32 + oyl) * 36 + oxl;
        ull a = 0ull;
        fma2(a, tc[0], gp0);
        fma2(a, tc[1], gp1);
        fma2(a, tc[2], gp2);
        fma2(a, tc[3], gp3);
        float2 y = *(float2*)&a;
        size_t base = ((size_t)(op * 2) * 512 + (oy0 + oyl)) * 512 + (ox0 + oxl);
        og[base] = y.x;
        og[base + 262144] = y.y;
    }
}

extern "C" void kernel_launch(void* const* d_in, const int* in_sizes, int n_in,
                              void* d_out, int out_size) {
    const float* x = (const float*)d_in[0];
    const float* f = (const float*)d_in[1];
    const float* w = (const float*)d_in[2];
    float* out = (float*)d_out;

    cudaFuncSetAttribute(conv_resample_kernel,
                         cudaFuncAttributeMaxDynamicSharedMemorySize, SMEM_BYTES);
    dim3 grid(256, 8, 4);   // 16x16 low-res tiles, groups, batch
    conv_resample_kernel<<<grid, THREADS, SMEM_BYTES>>>(x, f, w, out);
}

// round 4
// speedup vs baseline: 1.3312x; 1.3312x over previous
#include <cuda_runtime.h>
#include <cstdint>

typedef unsigned long long ull;

#define THREADS 512
// smem layout (bytes):
//   xb  floats [16 ic][19 rows][34 cols]        = 41344
//   wb  ull    [16 ic][8 op][10]                = 10240
//   z2  ull    [8 op][36 rows][2 px][34 cols]   = 156672
#define XB_RS  34
#define WB_OFF 41344
#define Z2_OFF 51584
#define Z2_ROW 68                 // ull per z2 row (2 planes x 34)
#define Z2_OP  (36 * Z2_ROW)
#define SMEM_BYTES (Z2_OFF + 156672)   // 208256

__device__ __forceinline__ ull pack2(float v) {
    ull r; asm("mov.b64 %0, {%1, %1};" : "=l"(r) : "f"(v)); return r;
}
__device__ __forceinline__ ull packf2(float a, float b) {
    ull r; asm("mov.b64 %0, {%1, %2};" : "=l"(r) : "f"(a), "f"(b)); return r;
}
__device__ __forceinline__ void fma2(ull &acc, ull a, ull b) {
    asm("fma.rn.f32x2 %0, %1, %2, %0;" : "+l"(acc) : "l"(a), "l"(b));
}

// One stage-2 unit: ocpair `op`, position rows 6*rb .. 6*rb+5, lane = position col.
// acc packed f32x2 over the oc pair; 4 phase accumulators per position row.
__device__ __forceinline__ void stage2_unit(int op, int rb, int ln,
                                            const float* xb, const ull* wb, ull* zb) {
    const int ar0 = rb * 6;
    ull acc[6][4];
#pragma unroll
    for (int r = 0; r < 6; ++r) { acc[r][0] = acc[r][1] = acc[r][2] = acc[r][3] = 0ull; }

#pragma unroll 2
    for (int ic = 0; ic < 16; ++ic) {
        const ull* wp = wb + (ic * 8 + op) * 10;          // warp-uniform -> broadcast LDS
        ull w0 = wp[0], w1 = wp[1], w2 = wp[2], w3 = wp[3], w4 = wp[4],
            w5 = wp[5], w6 = wp[6], w7 = wp[7], w8 = wp[8];
        const float* xr = xb + (ic * 19 + ar0) * XB_RS + ln;
        ull xa = pack2(xr[0]), xbv = pack2(xr[1]);
#pragma unroll
        for (int r = 0; r < 6; ++r) {
            ull ya = pack2(xr[(r + 1) * XB_RS]);
            ull yb = pack2(xr[(r + 1) * XB_RS + 1]);
            // phase (py,px): P00 taps w0,w2,w6,w8; P01 w1,w7; P10 w3,w5; P11 w4
            fma2(acc[r][0], xa,  w0); fma2(acc[r][0], xbv, w2);
            fma2(acc[r][0], ya,  w6); fma2(acc[r][0], yb,  w8);
            fma2(acc[r][1], xbv, w1); fma2(acc[r][1], yb,  w7);
            fma2(acc[r][2], ya,  w3); fma2(acc[r][2], yb,  w5);
            fma2(acc[r][3], yb,  w4);
            xa = ya; xbv = yb;
        }
    }
    // store z2: [op][zr][px][col], lane-stride 1 -> conflict-free
    ull* zrow = zb + (size_t)op * Z2_OP + ln;
#pragma unroll
    for (int r = 0; r < 6; ++r) {
        int zr0 = 2 * (ar0 + r);
        zrow[(size_t)zr0 * Z2_ROW]            = acc[r][0];  // py0 px0
        zrow[(size_t)zr0 * Z2_ROW + 34]       = acc[r][1];  // py0 px1
        zrow[(size_t)(zr0 + 1) * Z2_ROW]      = acc[r][2];  // py1 px0
        zrow[(size_t)(zr0 + 1) * Z2_ROW + 34] = acc[r][3];  // py1 px1
    }
}

__global__ __launch_bounds__(THREADS, 1)
void conv_resample_v4(const float* __restrict__ x, const float* __restrict__ f,
                      const float* __restrict__ w, float* __restrict__ out) {
    extern __shared__ char sm[];
    float* xb = (float*)sm;
    ull* wb = (ull*)(sm + WB_OFF);
    ull* zb = (ull*)(sm + Z2_OFF);

    const int tid = threadIdx.x;
    const int wid = tid >> 5, ln = tid & 31;
    const int ctile = blockIdx.x % 9, rtile = blockIdx.x / 9;
    const int g = blockIdx.y, n = blockIdx.z;
    const int a0 = rtile * 16;          // low-res row origin
    const int b0 = ctile * 30;          // low-res col origin (last tile clamped)

    // ---- stage 1: x tile [16 ic][19][33] with zero halo/clamp ----
    const float* xg = x + ((size_t)(n * 128 + g * 16)) * 65536;
    for (int i = tid; i < 16 * 19 * 33; i += THREADS) {
        int c = i % 33;
        int rr = (i / 33) % 19;
        int ic = i / (33 * 19);
        int gm = a0 - 2 + rr, gq = b0 - 2 + c;
        float v = (gm >= 0 && gm < 256 && gq >= 0 && gq < 256)
                    ? xg[ic * 65536 + gm * 256 + gq] : 0.f;
        xb[(ic * 19 + rr) * XB_RS + c] = v;
    }
    // ---- stage 1b: weights as oc-pair f32x2, [ic][op][tap] ----
    const float* wgp = w + (size_t)g * 16 * 144;
    for (int i = tid; i < 16 * 8 * 9; i += THREADS) {
        int t = i % 9;
        int op = (i / 9) & 7;
        int ic = i / 72;
        float w0 = wgp[(op * 2 + 0) * 144 + ic * 9 + t];
        float w1 = wgp[(op * 2 + 1) * 144 + ic * 9 + t];
        wb[(ic * 8 + op) * 10 + t] = packf2(w0, w1);
    }
    // FIR coeffs (g[a] = 2*f[3-a])
    float f0 = __ldg(f), f1 = __ldg(f + 1), f2 = __ldg(f + 2), f3 = __ldg(f + 3);
    ull gq0 = pack2(2.f * f3), gq1 = pack2(2.f * f2),
        gq2 = pack2(2.f * f1), gq3 = pack2(2.f * f0);
    __syncthreads();

    // ---- stage 2: 24 units (8 op x 3 row-blocks) over 16 warps ----
    for (int u = wid; u < 24; u += 16)
        stage2_unit(u & 7, u >> 3, ln, xb, wb, zb);
    __syncthreads();

    // ---- stage 3: register-streaming separable FIR; warp = (op, row-half) ----
    const int op3 = wid & 7, rh = wid >> 3;
    const ull* zcol = zb + (size_t)op3 * Z2_OP;
    const int oy0 = rh * 16;
    float* og = out + ((size_t)(n * 128 + g * 16 + op3 * 2)) * 262144
                    + (size_t)(2 * a0) * 512 + 2 * b0;

#pragma unroll 1
    for (int half = 0; half < 2; ++half) {
        int ox = half * 32 + ln;
        bool valid = (ox < 60) && (2 * b0 + ox < 512);
        int oxc = (ox < 60) ? ox : 59;
        int zc = oxc + 1;
        int zo0 = (zc & 1) * 34 + (zc >> 1); ++zc;
        int zo1 = (zc & 1) * 34 + (zc >> 1); ++zc;
        int zo2 = (zc & 1) * 34 + (zc >> 1); ++zc;
        int zo3 = (zc & 1) * 34 + (zc >> 1);

        const ull* zp = zcol + (size_t)(oy0 + 1) * Z2_ROW;
        ull tb0, tb1, tb2;
        { ull t = 0; fma2(t, zp[zo0], gq0); fma2(t, zp[zo1], gq1);
          fma2(t, zp[zo2], gq2); fma2(t, zp[zo3], gq3); tb0 = t; zp += Z2_ROW; }
        { ull t = 0; fma2(t, zp[zo0], gq0); fma2(t, zp[zo1], gq1);
          fma2(t, zp[zo2], gq2); fma2(t, zp[zo3], gq3); tb1 = t; zp += Z2_ROW; }
        { ull t = 0; fma2(t, zp[zo0], gq0); fma2(t, zp[zo1], gq1);
          fma2(t, zp[zo2], gq2); fma2(t, zp[zo3], gq3); tb2 = t; zp += Z2_ROW; }

#pragma unroll 4
        for (int oyl = 0; oyl < 16; ++oyl) {
            ull t = 0;
            fma2(t, zp[zo0], gq0); fma2(t, zp[zo1], gq1);
            fma2(t, zp[zo2], gq2); fma2(t, zp[zo3], gq3);
            zp += Z2_ROW;
            ull y = 0;
            fma2(y, tb0, gq0); fma2(y, tb1, gq1);
            fma2(y, tb2, gq2); fma2(y, t, gq3);
            tb0 = tb1; tb1 = tb2; tb2 = t;
            if (valid) {
                float2 yy = *(float2*)&y;
                size_t o = (size_t)(oy0 + oyl) * 512 + ox;
                og[o] = yy.x;
                og[o + 262144] = yy.y;
            }
        }
    }
}

extern "C" void kernel_launch(void* const* d_in, const int* in_sizes, int n_in,
                              void* d_out, int out_size) {
    const float* x = (const float*)d_in[0];
    const float* f = (const float*)d_in[1];
    const float* w = (const float*)d_in[2];
    float* out = (float*)d_out;

    cudaFuncSetAttribute(conv_resample_v4,
                         cudaFuncAttributeMaxDynamicSharedMemorySize, SMEM_BYTES);
    dim3 grid(9 * 16, 8, 4);   // (col-tiles x row-tiles, groups, batch) = 4608 CTAs
    conv_resample_v4<<<grid, THREADS, SMEM_BYTES>>>(x, f, w, out);
}

// round 5
// speedup vs baseline: 1.4383x; 1.0804x over previous
#include <cuda_runtime.h>
#include <cstdint>

typedef unsigned long long ull;
#define THREADS 512

// tile: 14x14 low-res -> 28x28 output
// smem: xb float [16 ic][17 r][18 pad]      @ 0      = 19584 B
//       wb ull   [16 ic][8 op][10 pad]      @ 19584  = 10240 B
//       z2 ull   [8 op][32 zr][2 px][17]    @ 29824  = 69632 B
#define XB_R   18
#define WB_OFF 19584
#define Z2_OFF 29824
#define Z2_PL  17
#define Z2_ROW 34
#define Z2_OP  (32 * Z2_ROW)
#define SMEM_BYTES 99456

__device__ __forceinline__ ull pack2(float v) {
    ull r; asm("mov.b64 %0, {%1, %1};" : "=l"(r) : "f"(v)); return r;
}
__device__ __forceinline__ ull packf2(float a, float b) {
    ull r; asm("mov.b64 %0, {%1, %2};" : "=l"(r) : "f"(a), "f"(b)); return r;
}
__device__ __forceinline__ void fma2(ull &acc, ull a, ull b) {
    asm("fma.rn.f32x2 %0, %1, %2, %0;" : "+l"(acc) : "l"(a), "l"(b));
}

__global__ __launch_bounds__(THREADS, 2)
void conv_resample_v5(const float* __restrict__ x, const float* __restrict__ f,
                      const float* __restrict__ w, float* __restrict__ out) {
    extern __shared__ char sm[];
    float* xb = (float*)sm;
    ull* wb = (ull*)(sm + WB_OFF);
    ull* zb = (ull*)(sm + Z2_OFF);

    const int tid = threadIdx.x;
    const int wid = tid >> 5, ln = tid & 31;
    const int rt = blockIdx.x / 19, ct = blockIdx.x % 19;
    const int g = blockIdx.y, n = blockIdx.z;
    const int a0 = rt * 14, b0 = ct * 14;

    // ---- stage 1: x tile [16 ic][17][17] with zero halo ----
    const float* xg = x + ((size_t)(n * 128 + g * 16)) * 65536;
    for (int i = tid; i < 16 * 17 * 17; i += THREADS) {
        int c = i % 17;
        int rr = (i / 17) % 17;
        int ic = i / 289;
        int gm = a0 - 2 + rr, gq = b0 - 2 + c;
        float v = (gm >= 0 && gm < 256 && gq >= 0 && gq < 256)
                    ? xg[ic * 65536 + gm * 256 + gq] : 0.f;
        xb[(ic * 17 + rr) * XB_R + c] = v;
    }
    // ---- weights as oc-pair f32x2: [ic][op][tap] ----
    const float* wgp = w + (size_t)g * 16 * 144;
    for (int i = tid; i < 16 * 8 * 9; i += THREADS) {
        int t = i % 9;
        int op = (i / 9) & 7;
        int ic = i / 72;
        wb[(ic * 8 + op) * 10 + t] =
            packf2(wgp[(op * 2 + 0) * 144 + ic * 9 + t],
                   wgp[(op * 2 + 1) * 144 + ic * 9 + t]);
    }
    float f0 = __ldg(f), f1 = __ldg(f + 1), f2 = __ldg(f + 2), f3 = __ldg(f + 3);
    ull gq0 = pack2(2.f * f3), gq1 = pack2(2.f * f2),
        gq2 = pack2(2.f * f1), gq3 = pack2(2.f * f0);
    __syncthreads();

    // ---- stage 2: 16 units = (4 op-groups) x (4 row-blocks); lane = (op-half, 16 cols) ----
    {
        const int opg = wid & 3, rb = wid >> 2;
        const int op = opg * 2 + (ln >> 4);
        const int pc = ln & 15;
        const int ar0 = rb * 4;

        ull acc[4][4];
#pragma unroll
        for (int r = 0; r < 4; ++r) { acc[r][0] = acc[r][1] = acc[r][2] = acc[r][3] = 0ull; }

#pragma unroll 4
        for (int ic = 0; ic < 16; ++ic) {
            const ull* wp = wb + (ic * 8 + op) * 10;
            ull w0 = wp[0], w1 = wp[1], w2 = wp[2], w3 = wp[3], w4 = wp[4],
                w5 = wp[5], w6 = wp[6], w7 = wp[7], w8 = wp[8];
            const float* xr = xb + (ic * 17 + ar0) * XB_R + pc;
            ull xa = pack2(xr[0]), xbv = pack2(xr[1]);
#pragma unroll
            for (int r = 0; r < 4; ++r) {
                ull ya = pack2(xr[(r + 1) * XB_R]);
                ull yb = pack2(xr[(r + 1) * XB_R + 1]);
                fma2(acc[r][0], xa,  w0); fma2(acc[r][0], xbv, w2);
                fma2(acc[r][0], ya,  w6); fma2(acc[r][0], yb,  w8);
                fma2(acc[r][1], xbv, w1); fma2(acc[r][1], yb,  w7);
                fma2(acc[r][2], ya,  w3); fma2(acc[r][2], yb,  w5);
                fma2(acc[r][3], yb,  w4);
                xa = ya; xbv = yb;
            }
        }
        ull* zo = zb + (size_t)op * Z2_OP + pc;
#pragma unroll
        for (int r = 0; r < 4; ++r) {
            int zr0 = 2 * (ar0 + r);
            zo[(size_t)zr0 * Z2_ROW]                = acc[r][0];   // py0 px0
            zo[(size_t)zr0 * Z2_ROW + Z2_PL]        = acc[r][1];   // py0 px1
            zo[(size_t)(zr0 + 1) * Z2_ROW]          = acc[r][2];   // py1 px0
            zo[(size_t)(zr0 + 1) * Z2_ROW + Z2_PL]  = acc[r][3];   // py1 px1
        }
    }
    __syncthreads();

    // ---- stage 3: register-streaming separable FIR; warp = (op, row-half) ----
    const int op3 = wid & 7, rh = wid >> 3;
    const int oy0 = rh * 14;
    const bool lane_ok = (ln < 28);
    const int oxc = lane_ok ? ln : 27;

    int zc = oxc + 1;
    int zo0 = (zc & 1) * Z2_PL + (zc >> 1); ++zc;
    int zo1 = (zc & 1) * Z2_PL + (zc >> 1); ++zc;
    int zo2 = (zc & 1) * Z2_PL + (zc >> 1); ++zc;
    int zo3 = (zc & 1) * Z2_PL + (zc >> 1);

    const ull* zp = zb + (size_t)op3 * Z2_OP + (size_t)(oy0 + 1) * Z2_ROW;
    ull tb0, tb1, tb2;
    { ull t = 0; fma2(t, zp[zo0], gq0); fma2(t, zp[zo1], gq1);
      fma2(t, zp[zo2], gq2); fma2(t, zp[zo3], gq3); tb0 = t; zp += Z2_ROW; }
    { ull t = 0; fma2(t, zp[zo0], gq0); fma2(t, zp[zo1], gq1);
      fma2(t, zp[zo2], gq2); fma2(t, zp[zo3], gq3); tb1 = t; zp += Z2_ROW; }
    { ull t = 0; fma2(t, zp[zo0], gq0); fma2(t, zp[zo1], gq1);
      fma2(t, zp[zo2], gq2); fma2(t, zp[zo3], gq3); tb2 = t; zp += Z2_ROW; }

    const bool col_ok = lane_ok && (2 * b0 + ln < 512);
    float* og = out + ((size_t)(n * 128 + g * 16 + op3 * 2)) * 262144
                    + (size_t)(2 * a0) * 512 + 2 * b0;

#pragma unroll 7
    for (int oyl = 0; oyl < 14; ++oyl) {
        ull t = 0;
        fma2(t, zp[zo0], gq0); fma2(t, zp[zo1], gq1);
        fma2(t, zp[zo2], gq2); fma2(t, zp[zo3], gq3);
        zp += Z2_ROW;
        ull y = 0;
        fma2(y, tb0, gq0); fma2(y, tb1, gq1);
        fma2(y, tb2, gq2); fma2(y, t, gq3);
        tb0 = tb1; tb1 = tb2; tb2 = t;
        int oy = oy0 + oyl;
        if (col_ok && (2 * a0 + oy < 512)) {
            float2 yy = *(float2*)&y;
            size_t o = (size_t)oy * 512 + ln;
            og[o] = yy.x;
            og[o + 262144] = yy.y;
        }
    }
}

extern "C" void kernel_launch(void* const* d_in, const int* in_sizes, int n_in,
                              void* d_out, int out_size) {
    const float* x = (const float*)d_in[0];
    const float* f = (const float*)d_in[1];
    const float* w = (const float*)d_in[2];
    float* out = (float*)d_out;

    cudaFuncSetAttribute(conv_resample_v5,
                         cudaFuncAttributeMaxDynamicSharedMemorySize, SMEM_BYTES);
    dim3 grid(19 * 19, 8, 4);   // 361 tiles x groups x batch = 11552 CTAs
    conv_resample_v5<<<grid, THREADS, SMEM_BYTES>>>(x, f, w, out);
}